// round 12
// baseline (speedup 1.0000x reference)
#include <cuda_runtime.h>
#include <cuda_bf16.h>
#include <cstdint>

#define NTOK 8192
#define DIMK 1024
#define HID  2560
#define NE   4
#define RS   40   // smem row stride in bf16 units (80B -> conflict-free)

// ---------------- static scratch (no runtime allocation allowed) ------------
__device__ int   d_cnt[NE];
__device__ int   d_idx[NE * NTOK];
__device__ int   d_tok_e[NTOK * 2];
__device__ int   d_tok_s[NTOK * 2];
__device__ float d_tok_w[NTOK * 2];

__device__ __nv_bfloat16 d_xh[(size_t)NTOK * DIMK];
__device__ __nv_bfloat16 d_xl[(size_t)NTOK * DIMK];
__device__ __nv_bfloat16 d_w1h[(size_t)NE * HID * DIMK];
__device__ __nv_bfloat16 d_w1l[(size_t)NE * HID * DIMK];
__device__ __nv_bfloat16 d_w3h[(size_t)NE * HID * DIMK];
__device__ __nv_bfloat16 d_w3l[(size_t)NE * HID * DIMK];
__device__ __nv_bfloat16 d_w2h[(size_t)NE * DIMK * HID];
__device__ __nv_bfloat16 d_w2l[(size_t)NE * DIMK * HID];
__device__ __nv_bfloat16 d_Hh[(size_t)NE * NTOK * HID];
__device__ __nv_bfloat16 d_Hl[(size_t)NE * NTOK * HID];
__device__ float d_Y[(size_t)NE * NTOK * DIMK];

// ---------------- helpers ---------------------------------------------------
__device__ __forceinline__ void mma_bf16(float c[4], const uint32_t a[4], const uint32_t b[2]) {
    asm volatile(
        "mma.sync.aligned.m16n8k16.row.col.f32.bf16.bf16.f32 "
        "{%0,%1,%2,%3},{%4,%5,%6,%7},{%8,%9},{%0,%1,%2,%3};\n"
        : "+f"(c[0]), "+f"(c[1]), "+f"(c[2]), "+f"(c[3])
        : "r"(a[0]), "r"(a[1]), "r"(a[2]), "r"(a[3]), "r"(b[0]), "r"(b[1]));
}
// bf16x3: C += Ah*Bh + Ah*Bl + Al*Bh
__device__ __forceinline__ void mma3(float c[4], const uint32_t ah[4], const uint32_t al[4],
                                     const uint32_t bh[2], const uint32_t bl[2]) {
    mma_bf16(c, ah, bh);
    mma_bf16(c, ah, bl);
    mma_bf16(c, al, bh);
}
__device__ __forceinline__ void ldmx4(uint32_t r[4], uint32_t saddr) {
    asm volatile("ldmatrix.sync.aligned.m8n8.x4.shared.b16 {%0,%1,%2,%3}, [%4];"
                 : "=r"(r[0]), "=r"(r[1]), "=r"(r[2]), "=r"(r[3]) : "r"(saddr));
}
__device__ __forceinline__ uint32_t s2u(const void* p) {
    return (uint32_t)__cvta_generic_to_shared(p);
}
// 16B async copy of bf16 data; pred=false -> zero-fill
__device__ __forceinline__ void cp16b(__nv_bfloat16* smem_dst, const float4* gsrc, bool pred) {
    uint32_t s = s2u(smem_dst);
    int sz = pred ? 16 : 0;
    asm volatile("cp.async.cg.shared.global [%0], [%1], 16, %2;\n" :: "r"(s), "l"(gsrc), "r"(sz));
}
#define CP_COMMIT() asm volatile("cp.async.commit_group;\n" ::: "memory")
#define CP_WAIT0()  asm volatile("cp.async.wait_group 0;\n" ::: "memory")

__device__ __forceinline__ float silu_f(float a) { return a / (1.f + expf(-a)); }

__device__ __forceinline__ void bsplit(float v, __nv_bfloat16& hi, __nv_bfloat16& lo) {
    hi = __float2bfloat16(v);
    lo = __float2bfloat16(v - __bfloat162float(hi));
}

// ---------------- kernels ---------------------------------------------------
__global__ void zero_cnt_kernel() {
    if (threadIdx.x < NE) d_cnt[threadIdx.x] = 0;
}

// elementwise fp32 -> bf16 hi/lo decomposition (vectorized x4)
__global__ __launch_bounds__(256) void split_kernel(const float* __restrict__ in, int which, int n4) {
    int i = blockIdx.x * blockDim.x + threadIdx.x;
    if (i >= n4) return;
    __nv_bfloat16 *hi, *lo;
    switch (which) {
        case 0: hi = d_xh;  lo = d_xl;  break;
        case 1: hi = d_w1h; lo = d_w1l; break;
        case 2: hi = d_w3h; lo = d_w3l; break;
        default: hi = d_w2h; lo = d_w2l; break;
    }
    float4 v = reinterpret_cast<const float4*>(in)[i];
    __nv_bfloat16 h0, h1, h2, h3, l0, l1, l2, l3;
    bsplit(v.x, h0, l0); bsplit(v.y, h1, l1);
    bsplit(v.z, h2, l2); bsplit(v.w, h3, l3);
    __nv_bfloat162* hp = reinterpret_cast<__nv_bfloat162*>(hi);
    __nv_bfloat162* lp = reinterpret_cast<__nv_bfloat162*>(lo);
    hp[2 * i]     = __nv_bfloat162(h0, h1);
    hp[2 * i + 1] = __nv_bfloat162(h2, h3);
    lp[2 * i]     = __nv_bfloat162(l0, l1);
    lp[2 * i + 1] = __nv_bfloat162(l2, l3);
}

// one warp per token: logits over 4 experts, softmax -> top2 -> renorm, scatter
__global__ __launch_bounds__(256) void gate_kernel(const float* __restrict__ x,
                                                   const float* __restrict__ gw) {
    __shared__ float sgw[NE * DIMK];
    const int tid = threadIdx.x;
    #pragma unroll
    for (int it = 0; it < 4; it++) {
        int i = tid + it * 256;
        reinterpret_cast<float4*>(sgw)[i] = reinterpret_cast<const float4*>(gw)[i];
    }
    __syncthreads();

    const int warp = tid >> 5, lane = tid & 31;
    const int n = blockIdx.x * 8 + warp;
    const float4* xr = reinterpret_cast<const float4*>(x + (size_t)n * DIMK);
    const float4* g4 = reinterpret_cast<const float4*>(sgw);

    float acc[NE] = {0.f, 0.f, 0.f, 0.f};
    #pragma unroll
    for (int j = lane; j < DIMK / 4; j += 32) {
        float4 xv = xr[j];
        #pragma unroll
        for (int e = 0; e < NE; e++) {
            float4 gv = g4[e * (DIMK / 4) + j];
            acc[e] += xv.x * gv.x + xv.y * gv.y + xv.z * gv.z + xv.w * gv.w;
        }
    }
    #pragma unroll
    for (int e = 0; e < NE; e++)
        #pragma unroll
        for (int off = 16; off > 0; off >>= 1)
            acc[e] += __shfl_xor_sync(0xffffffffu, acc[e], off);

    if (lane == 0) {
        int i0 = 0;
        #pragma unroll
        for (int e = 1; e < NE; e++) if (acc[e] > acc[i0]) i0 = e;
        int i1 = -1;
        #pragma unroll
        for (int e = 0; e < NE; e++)
            if (e != i0 && (i1 < 0 || acc[e] > acc[i1])) i1 = e;
        float p1 = expf(acc[i1] - acc[i0]);
        float inv = 1.f / (1.f + p1);
        float w0 = inv, w1 = p1 * inv;

        int s0 = atomicAdd(&d_cnt[i0], 1);
        d_idx[i0 * NTOK + s0] = n;
        int s1 = atomicAdd(&d_cnt[i1], 1);
        d_idx[i1 * NTOK + s1] = n;

        d_tok_e[2 * n] = i0;  d_tok_e[2 * n + 1] = i1;
        d_tok_s[2 * n] = s0;  d_tok_s[2 * n + 1] = s1;
        d_tok_w[2 * n] = w0;  d_tok_w[2 * n + 1] = w1;
    }
}

// ---------------- GEMM1: h = silu(Xg@W1^T) * (Xg@W3^T), bf16x3 ---------------
// Block 128(M) x 64(N) x 32(K), 8 warps (4x2), warp tile 32x32, 2-stage cp.async,
// ldmatrix fragment loads.
// smem per stage (bf16): [Ah 128*RS][Al 128*RS][B1h 64*RS][B1l][B3h][B3l]
#define F1_AL  (128 * RS)
#define F1_B1H (256 * RS)
#define F1_B1L (320 * RS)
#define F1_B3H (384 * RS)
#define F1_B3L (448 * RS)
#define F1_ST  (512 * RS)

__global__ __launch_bounds__(256) void ffn1_kernel() {
    const int e = blockIdx.z;
    const int me = d_cnt[e];
    const int m0 = blockIdx.y * 128;
    if (m0 >= me) return;
    const int n0 = blockIdx.x * 64;

    extern __shared__ __align__(16) __nv_bfloat16 sm[];

    const int tid = threadIdx.x;
    const int warp = tid >> 5, lane = tid & 31;
    const int wm = warp >> 1, wn = warp & 1;   // 4 x 2 warp grid
    const int g = lane >> 2, t = lane & 3;

    // ldmatrix lane geometry: row within 16-block + col half selector
    const int lr8 = (lane & 7) + ((lane >> 3) & 1) * 8;
    const int lc8 = (lane >> 4) * 8;

    const int* idxs = d_idx + e * NTOK;
    const float4* xh4 = reinterpret_cast<const float4*>(d_xh);
    const float4* xl4 = reinterpret_cast<const float4*>(d_xl);
    const float4* w1h4 = reinterpret_cast<const float4*>(d_w1h + (size_t)e * HID * DIMK);
    const float4* w1l4 = reinterpret_cast<const float4*>(d_w1l + (size_t)e * HID * DIMK);
    const float4* w3h4 = reinterpret_cast<const float4*>(d_w3h + (size_t)e * HID * DIMK);
    const float4* w3l4 = reinterpret_cast<const float4*>(d_w3l + (size_t)e * HID * DIMK);

    // loader geometry: ch = 16B chunk along k (8 bf16), rr = row
    const int ch = tid & 3;
    const int rr = tid >> 2;   // 0..63
    bool aok[2]; size_t arow[2];
    #pragma unroll
    for (int it = 0; it < 2; it++) {
        int grow = m0 + rr + it * 64;
        aok[it] = grow < me;
        int gi = aok[it] ? idxs[grow] : 0;
        arow[it] = (size_t)gi * (DIMK / 8);
    }
    const size_t brow = (size_t)(n0 + rr) * (DIMK / 8);

    auto load_tiles = [&](int k0, int st) {
        __nv_bfloat16* bs = sm + st * F1_ST;
        const int kq = (k0 >> 3) + ch;
        #pragma unroll
        for (int it = 0; it < 2; it++) {
            int r = rr + it * 64;
            cp16b(bs + r * RS + ch * 8,          xh4 + arow[it] + kq, aok[it]);
            cp16b(bs + F1_AL + r * RS + ch * 8,  xl4 + arow[it] + kq, aok[it]);
        }
        cp16b(bs + F1_B1H + rr * RS + ch * 8, w1h4 + brow + kq, true);
        cp16b(bs + F1_B1L + rr * RS + ch * 8, w1l4 + brow + kq, true);
        cp16b(bs + F1_B3H + rr * RS + ch * 8, w3h4 + brow + kq, true);
        cp16b(bs + F1_B3L + rr * RS + ch * 8, w3l4 + brow + kq, true);
    };

    float acc1[2][4][4] = {}, acc3[2][4][4] = {};

    load_tiles(0, 0);
    CP_COMMIT();
    CP_WAIT0();
    __syncthreads();

    int s = 0;
    for (int k0 = 0; k0 < DIMK; k0 += 32) {
        const bool pf = (k0 + 32) < DIMK;
        if (pf) { load_tiles(k0 + 32, s ^ 1); CP_COMMIT(); }

        const uint32_t bsu = s2u(sm + s * F1_ST);
        #pragma unroll
        for (int kk = 0; kk < 2; kk++) {          // two k16 steps per 32-slab
            const int kb = kk * 16;
            // A fragments via ldmatrix.x4 (hi + lo planes)
            uint32_t ah[2][4], al[2][4];
            #pragma unroll
            for (int mi = 0; mi < 2; mi++) {
                const uint32_t a_off =
                    ((uint32_t)((wm * 32 + mi * 16 + lr8) * RS + kb + lc8)) * 2u;
                ldmx4(ah[mi], bsu + a_off);
                ldmx4(al[mi], bsu + a_off + F1_AL * 2u);
            }
            // B fragments: each x4 covers two n 8-blocks
            uint32_t b1h[2][4], b1l[2][4], b3h[2][4], b3l[2][4];
            #pragma unroll
            for (int q = 0; q < 2; q++) {
                const uint32_t b_off =
                    ((uint32_t)((wn * 32 + q * 16 + lr8) * RS + kb + lc8)) * 2u;
                ldmx4(b1h[q], bsu + b_off + F1_B1H * 2u);
                ldmx4(b1l[q], bsu + b_off + F1_B1L * 2u);
                ldmx4(b3h[q], bsu + b_off + F1_B3H * 2u);
                ldmx4(b3l[q], bsu + b_off + F1_B3L * 2u);
            }
            #pragma unroll
            for (int q = 0; q < 2; q++)
                #pragma unroll
                for (int j = 0; j < 2; j++) {
                    const int ni = q * 2 + j;
                    uint32_t bh[2] = { b1h[q][j], b1h[q][j + 2] };
                    uint32_t bl[2] = { b1l[q][j], b1l[q][j + 2] };
                    #pragma unroll
                    for (int mi = 0; mi < 2; mi++)
                        mma3(acc1[mi][ni], ah[mi], al[mi], bh, bl);
                    uint32_t ch2[2] = { b3h[q][j], b3h[q][j + 2] };
                    uint32_t cl2[2] = { b3l[q][j], b3l[q][j + 2] };
                    #pragma unroll
                    for (int mi = 0; mi < 2; mi++)
                        mma3(acc3[mi][ni], ah[mi], al[mi], ch2, cl2);
                }
        }

        if (pf) CP_WAIT0();
        __syncthreads();
        s ^= 1;
    }

    // epilogue: h = silu(h1)*h3, store bf16 hi/lo pairs
    const size_t Hbase = (size_t)e * NTOK * HID;
    #pragma unroll
    for (int mi = 0; mi < 2; mi++)
        #pragma unroll
        for (int ni = 0; ni < 4; ni++) {
            int rbase = wm * 32 + mi * 16 + g;
            int cbase = wn * 32 + ni * 8 + t * 2;
            #pragma unroll
            for (int h2 = 0; h2 < 2; h2++) {
                int grow = m0 + rbase + h2 * 8;
                if (grow < me) {
                    float v0 = silu_f(acc1[mi][ni][h2 * 2 + 0]) * acc3[mi][ni][h2 * 2 + 0];
                    float v1 = silu_f(acc1[mi][ni][h2 * 2 + 1]) * acc3[mi][ni][h2 * 2 + 1];
                    __nv_bfloat16 h0, h1, l0, l1;
                    bsplit(v0, h0, l0);
                    bsplit(v1, h1, l1);
                    size_t off = Hbase + (size_t)grow * HID + n0 + cbase;
                    *reinterpret_cast<__nv_bfloat162*>(&d_Hh[off]) = __nv_bfloat162(h0, h1);
                    *reinterpret_cast<__nv_bfloat162*>(&d_Hl[off]) = __nv_bfloat162(l0, l1);
                }
            }
        }
}

// ---------------- GEMM2: Y = H @ W2^T, bf16x3 --------------------------------
// smem per stage (bf16): [Ah 128*RS][Al 128*RS][Bh 64*RS][Bl 64*RS]
#define F2_AL (128 * RS)
#define F2_BH (256 * RS)
#define F2_BL (320 * RS)
#define F2_ST (384 * RS)

__global__ __launch_bounds__(256, 2) void ffn2_kernel() {
    const int e = blockIdx.z;
    const int me = d_cnt[e];
    const int m0 = blockIdx.y * 128;
    if (m0 >= me) return;
    const int n0 = blockIdx.x * 64;

    extern __shared__ __align__(16) __nv_bfloat16 sm[];

    const int tid = threadIdx.x;
    const int warp = tid >> 5, lane = tid & 31;
    const int wm = warp >> 1, wn = warp & 1;
    const int g = lane >> 2, t = lane & 3;

    const int lr8 = (lane & 7) + ((lane >> 3) & 1) * 8;
    const int lc8 = (lane >> 4) * 8;

    const float4* Hh4 = reinterpret_cast<const float4*>(d_Hh + (size_t)e * NTOK * HID);
    const float4* Hl4 = reinterpret_cast<const float4*>(d_Hl + (size_t)e * NTOK * HID);
    const float4* w2h4 = reinterpret_cast<const float4*>(d_w2h + (size_t)e * DIMK * HID);
    const float4* w2l4 = reinterpret_cast<const float4*>(d_w2l + (size_t)e * DIMK * HID);

    const int ch = tid & 3;
    const int rr = tid >> 2;
    bool aok[2]; size_t arow[2];
    #pragma unroll
    for (int it = 0; it < 2; it++) {
        int grow = m0 + rr + it * 64;
        aok[it] = grow < me;
        arow[it] = (size_t)(aok[it] ? grow : 0) * (HID / 8);
    }
    const size_t brow = (size_t)(n0 + rr) * (HID / 8);

    auto load_tiles = [&](int k0, int st) {
        __nv_bfloat16* bs = sm + st * F2_ST;
        const int kq = (k0 >> 3) + ch;
        #pragma unroll
        for (int it = 0; it < 2; it++) {
            int r = rr + it * 64;
            cp16b(bs + r * RS + ch * 8,         Hh4 + arow[it] + kq, aok[it]);
            cp16b(bs + F2_AL + r * RS + ch * 8, Hl4 + arow[it] + kq, aok[it]);
        }
        cp16b(bs + F2_BH + rr * RS + ch * 8, w2h4 + brow + kq, true);
        cp16b(bs + F2_BL + rr * RS + ch * 8, w2l4 + brow + kq, true);
    };

    float acc[2][4][4] = {};

    load_tiles(0, 0);
    CP_COMMIT();
    CP_WAIT0();
    __syncthreads();

    int s = 0;
    for (int k0 = 0; k0 < HID; k0 += 32) {
        const bool pf = (k0 + 32) < HID;
        if (pf) { load_tiles(k0 + 32, s ^ 1); CP_COMMIT(); }

        const uint32_t bsu = s2u(sm + s * F2_ST);
        #pragma unroll
        for (int kk = 0; kk < 2; kk++) {
            const int kb = kk * 16;
            uint32_t ah[2][4], al[2][4];
            #pragma unroll
            for (int mi = 0; mi < 2; mi++) {
                const uint32_t a_off =
                    ((uint32_t)((wm * 32 + mi * 16 + lr8) * RS + kb + lc8)) * 2u;
                ldmx4(ah[mi], bsu + a_off);
                ldmx4(al[mi], bsu + a_off + F2_AL * 2u);
            }
            uint32_t bh4[2][4], bl4[2][4];
            #pragma unroll
            for (int q = 0; q < 2; q++) {
                const uint32_t b_off =
                    ((uint32_t)((wn * 32 + q * 16 + lr8) * RS + kb + lc8)) * 2u;
                ldmx4(bh4[q], bsu + b_off + F2_BH * 2u);
                ldmx4(bl4[q], bsu + b_off + F2_BL * 2u);
            }
            #pragma unroll
            for (int q = 0; q < 2; q++)
                #pragma unroll
                for (int j = 0; j < 2; j++) {
                    const int ni = q * 2 + j;
                    uint32_t bh[2] = { bh4[q][j], bh4[q][j + 2] };
                    uint32_t bl[2] = { bl4[q][j], bl4[q][j + 2] };
                    #pragma unroll
                    for (int mi = 0; mi < 2; mi++)
                        mma3(acc[mi][ni], ah[mi], al[mi], bh, bl);
                }
        }

        if (pf) CP_WAIT0();
        __syncthreads();
        s ^= 1;
    }

    float* Yrow = d_Y + (size_t)e * NTOK * DIMK;
    #pragma unroll
    for (int mi = 0; mi < 2; mi++)
        #pragma unroll
        for (int ni = 0; ni < 4; ni++) {
            int rbase = wm * 32 + mi * 16 + g;
            int cbase = wn * 32 + ni * 8 + t * 2;
            #pragma unroll
            for (int h2 = 0; h2 < 2; h2++) {
                int grow = m0 + rbase + h2 * 8;
                if (grow < me)
                    *reinterpret_cast<float2*>(&Yrow[(size_t)grow * DIMK + n0 + cbase]) =
                        make_float2(acc[mi][ni][h2 * 2 + 0], acc[mi][ni][h2 * 2 + 1]);
            }
        }
}

// out[n] = w0 * Y[e0][s0] + w1 * Y[e1][s1]
__global__ __launch_bounds__(256) void combine_kernel(float* __restrict__ out) {
    const int n = blockIdx.x;
    const int t = threadIdx.x;
    const int e0 = d_tok_e[2 * n], e1 = d_tok_e[2 * n + 1];
    const int s0 = d_tok_s[2 * n], s1 = d_tok_s[2 * n + 1];
    const float w0 = d_tok_w[2 * n], w1 = d_tok_w[2 * n + 1];

    const float4* y0 = reinterpret_cast<const float4*>(d_Y + ((size_t)e0 * NTOK + s0) * DIMK);
    const float4* y1 = reinterpret_cast<const float4*>(d_Y + ((size_t)e1 * NTOK + s1) * DIMK);
    float4 a = y0[t], b = y1[t];
    float4 r;
    r.x = w0 * a.x + w1 * b.x;
    r.y = w0 * a.y + w1 * b.y;
    r.z = w0 * a.z + w1 * b.z;
    r.w = w0 * a.w + w1 * b.w;
    reinterpret_cast<float4*>(out)[(size_t)n * (DIMK / 4) + t] = r;
}

__global__ void tail_zero_kernel(float* __restrict__ out, int start, int total) {
    int i = start + blockIdx.x * blockDim.x + threadIdx.x;
    if (i < total) out[i] = 0.f;
}

// ---------------- launch -----------------------------------------------------
extern "C" void kernel_launch(void* const* d_in, const int* in_sizes, int n_in,
                              void* d_out, int out_size) {
    const float* x    = (const float*)d_in[0];
    const float* gw   = (const float*)d_in[1];
    const float* w1   = (const float*)d_in[2];
    const float* w2   = (const float*)d_in[3];
    const float* w3   = (const float*)d_in[4];
    float* out = (float*)d_out;

    const int smem1 = 2 * F1_ST * 2;  // 81920 B
    const int smem2 = 2 * F2_ST * 2;  // 61440 B
    cudaFuncSetAttribute(ffn1_kernel, cudaFuncAttributeMaxDynamicSharedMemorySize, smem1);
    cudaFuncSetAttribute(ffn2_kernel, cudaFuncAttributeMaxDynamicSharedMemorySize, smem2);

    zero_cnt_kernel<<<1, 32>>>();
    gate_kernel<<<NTOK / 8, 256>>>(x, gw);

    const int n4x = NTOK * DIMK / 4;
    const int n4w = NE * HID * DIMK / 4;
    split_kernel<<<(n4x + 255) / 256, 256>>>(x,  0, n4x);
    split_kernel<<<(n4w + 255) / 256, 256>>>(w1, 1, n4w);
    split_kernel<<<(n4w + 255) / 256, 256>>>(w3, 2, n4w);
    split_kernel<<<(n4w + 255) / 256, 256>>>(w2, 3, n4w);

    ffn1_kernel<<<dim3(HID / 64, NTOK / 128, NE), 256, smem1>>>();
    ffn2_kernel<<<dim3(DIMK / 64, NTOK / 128, NE), 256, smem2>>>();
    combine_kernel<<<NTOK, 256>>>(out);

    int main_elems = NTOK * DIMK;
    if (out_size > main_elems) {
        int tail = out_size - main_elems;
        tail_zero_kernel<<<(tail + 255) / 256, 256>>>(out, main_elems, out_size);
    }
}

// round 13
// speedup vs baseline: 1.2082x; 1.2082x over previous
#include <cuda_runtime.h>
#include <cuda_bf16.h>
#include <cstdint>

#define NTOK 8192
#define DIMK 1024
#define HID  2560
#define NE   4
#define RS   40   // smem row stride in bf16 units (80B -> conflict-free LDS)

// ---------------- static scratch (no runtime allocation allowed) ------------
__device__ int   d_cnt[NE];
__device__ int   d_idx[NE * NTOK];
__device__ int   d_tok_e[NTOK * 2];
__device__ int   d_tok_s[NTOK * 2];
__device__ float d_tok_w[NTOK * 2];

__device__ __nv_bfloat16 d_xh[(size_t)NTOK * DIMK];
__device__ __nv_bfloat16 d_xl[(size_t)NTOK * DIMK];
__device__ __nv_bfloat16 d_w1h[(size_t)NE * HID * DIMK];
__device__ __nv_bfloat16 d_w1l[(size_t)NE * HID * DIMK];
__device__ __nv_bfloat16 d_w3h[(size_t)NE * HID * DIMK];
__device__ __nv_bfloat16 d_w3l[(size_t)NE * HID * DIMK];
__device__ __nv_bfloat16 d_w2h[(size_t)NE * DIMK * HID];
__device__ __nv_bfloat16 d_w2l[(size_t)NE * DIMK * HID];
__device__ __nv_bfloat16 d_Hh[(size_t)NE * NTOK * HID];
__device__ __nv_bfloat16 d_Hl[(size_t)NE * NTOK * HID];
__device__ float d_Y[(size_t)NE * NTOK * DIMK];

// ---------------- helpers ---------------------------------------------------
__device__ __forceinline__ void mma_bf16(float c[4], const uint32_t a[4], const uint32_t b[2]) {
    asm volatile(
        "mma.sync.aligned.m16n8k16.row.col.f32.bf16.bf16.f32 "
        "{%0,%1,%2,%3},{%4,%5,%6,%7},{%8,%9},{%0,%1,%2,%3};\n"
        : "+f"(c[0]), "+f"(c[1]), "+f"(c[2]), "+f"(c[3])
        : "r"(a[0]), "r"(a[1]), "r"(a[2]), "r"(a[3]), "r"(b[0]), "r"(b[1]));
}
// bf16x3: C += Ah*Bh + Ah*Bl + Al*Bh  (~fp32-accurate on bf16 units)
__device__ __forceinline__ void mma3(float c[4], const uint32_t ah[4], const uint32_t al[4],
                                     const uint32_t bh[2], const uint32_t bl[2]) {
    mma_bf16(c, ah, bh);
    mma_bf16(c, ah, bl);
    mma_bf16(c, al, bh);
}
__device__ __forceinline__ uint32_t lds32(const __nv_bfloat16* p) {
    return *reinterpret_cast<const uint32_t*>(p);
}
// 16B async copy of bf16 data; pred=false -> zero-fill
__device__ __forceinline__ void cp16b(__nv_bfloat16* smem_dst, const float4* gsrc, bool pred) {
    uint32_t s = (uint32_t)__cvta_generic_to_shared(smem_dst);
    int sz = pred ? 16 : 0;
    asm volatile("cp.async.cg.shared.global [%0], [%1], 16, %2;\n" :: "r"(s), "l"(gsrc), "r"(sz));
}
#define CP_COMMIT() asm volatile("cp.async.commit_group;\n" ::: "memory")
#define CP_WAIT0()  asm volatile("cp.async.wait_group 0;\n" ::: "memory")

__device__ __forceinline__ float silu_f(float a) { return a / (1.f + expf(-a)); }

__device__ __forceinline__ void bsplit(float v, __nv_bfloat16& hi, __nv_bfloat16& lo) {
    hi = __float2bfloat16(v);
    lo = __float2bfloat16(v - __bfloat162float(hi));
}

// ---------------- kernels ---------------------------------------------------
__global__ void zero_cnt_kernel() {
    if (threadIdx.x < NE) d_cnt[threadIdx.x] = 0;
}

// elementwise fp32 -> bf16 hi/lo decomposition (vectorized x4)
__global__ __launch_bounds__(256) void split_kernel(const float* __restrict__ in, int which, int n4) {
    int i = blockIdx.x * blockDim.x + threadIdx.x;
    if (i >= n4) return;
    __nv_bfloat16 *hi, *lo;
    switch (which) {
        case 0: hi = d_xh;  lo = d_xl;  break;
        case 1: hi = d_w1h; lo = d_w1l; break;
        case 2: hi = d_w3h; lo = d_w3l; break;
        default: hi = d_w2h; lo = d_w2l; break;
    }
    float4 v = reinterpret_cast<const float4*>(in)[i];
    __nv_bfloat16 h0, h1, h2, h3, l0, l1, l2, l3;
    bsplit(v.x, h0, l0); bsplit(v.y, h1, l1);
    bsplit(v.z, h2, l2); bsplit(v.w, h3, l3);
    __nv_bfloat162* hp = reinterpret_cast<__nv_bfloat162*>(hi);
    __nv_bfloat162* lp = reinterpret_cast<__nv_bfloat162*>(lo);
    hp[2 * i]     = __nv_bfloat162(h0, h1);
    hp[2 * i + 1] = __nv_bfloat162(h2, h3);
    lp[2 * i]     = __nv_bfloat162(l0, l1);
    lp[2 * i + 1] = __nv_bfloat162(l2, l3);
}

// one warp per token: logits over 4 experts, softmax -> top2 -> renorm, scatter
__global__ __launch_bounds__(256) void gate_kernel(const float* __restrict__ x,
                                                   const float* __restrict__ gw) {
    __shared__ float sgw[NE * DIMK];
    const int tid = threadIdx.x;
    #pragma unroll
    for (int it = 0; it < 4; it++) {
        int i = tid + it * 256;
        reinterpret_cast<float4*>(sgw)[i] = reinterpret_cast<const float4*>(gw)[i];
    }
    __syncthreads();

    const int warp = tid >> 5, lane = tid & 31;
    const int n = blockIdx.x * 8 + warp;
    const float4* xr = reinterpret_cast<const float4*>(x + (size_t)n * DIMK);
    const float4* g4 = reinterpret_cast<const float4*>(sgw);

    float acc[NE] = {0.f, 0.f, 0.f, 0.f};
    #pragma unroll
    for (int j = lane; j < DIMK / 4; j += 32) {
        float4 xv = xr[j];
        #pragma unroll
        for (int e = 0; e < NE; e++) {
            float4 gv = g4[e * (DIMK / 4) + j];
            acc[e] += xv.x * gv.x + xv.y * gv.y + xv.z * gv.z + xv.w * gv.w;
        }
    }
    #pragma unroll
    for (int e = 0; e < NE; e++)
        #pragma unroll
        for (int off = 16; off > 0; off >>= 1)
            acc[e] += __shfl_xor_sync(0xffffffffu, acc[e], off);

    if (lane == 0) {
        int i0 = 0;
        #pragma unroll
        for (int e = 1; e < NE; e++) if (acc[e] > acc[i0]) i0 = e;
        int i1 = -1;
        #pragma unroll
        for (int e = 0; e < NE; e++)
            if (e != i0 && (i1 < 0 || acc[e] > acc[i1])) i1 = e;
        float p1 = expf(acc[i1] - acc[i0]);
        float inv = 1.f / (1.f + p1);
        float w0 = inv, w1 = p1 * inv;

        int s0 = atomicAdd(&d_cnt[i0], 1);
        d_idx[i0 * NTOK + s0] = n;
        int s1 = atomicAdd(&d_cnt[i1], 1);
        d_idx[i1 * NTOK + s1] = n;

        d_tok_e[2 * n] = i0;  d_tok_e[2 * n + 1] = i1;
        d_tok_s[2 * n] = s0;  d_tok_s[2 * n + 1] = s1;
        d_tok_w[2 * n] = w0;  d_tok_w[2 * n + 1] = w1;
    }
}

// ---------------- GEMM1: h = silu(Xg@W1^T) * (Xg@W3^T), bf16x3 ---------------
// Block 128(M) x 64(N) x 32(K), 8 warps (4x2), warp tile 32x32, 2-stage cp.async.
// smem per stage (bf16): [Ah 128*RS][Al 128*RS][B1h 64*RS][B1l][B3h][B3l]
#define F1_AL  (128 * RS)
#define F1_B1H (256 * RS)
#define F1_B1L (320 * RS)
#define F1_B3H (384 * RS)
#define F1_B3L (448 * RS)
#define F1_ST  (512 * RS)

__global__ __launch_bounds__(256, 2) void ffn1_kernel() {
    const int e = blockIdx.z;
    const int me = d_cnt[e];
    const int m0 = blockIdx.y * 128;
    if (m0 >= me) return;
    const int n0 = blockIdx.x * 64;

    extern __shared__ __align__(16) __nv_bfloat16 sm[];

    const int tid = threadIdx.x;
    const int warp = tid >> 5, lane = tid & 31;
    const int wm = warp >> 1, wn = warp & 1;   // 4 x 2 warp grid
    const int g = lane >> 2, t = lane & 3;

    const int* idxs = d_idx + e * NTOK;
    const float4* xh4 = reinterpret_cast<const float4*>(d_xh);
    const float4* xl4 = reinterpret_cast<const float4*>(d_xl);
    const float4* w1h4 = reinterpret_cast<const float4*>(d_w1h + (size_t)e * HID * DIMK);
    const float4* w1l4 = reinterpret_cast<const float4*>(d_w1l + (size_t)e * HID * DIMK);
    const float4* w3h4 = reinterpret_cast<const float4*>(d_w3h + (size_t)e * HID * DIMK);
    const float4* w3l4 = reinterpret_cast<const float4*>(d_w3l + (size_t)e * HID * DIMK);

    // loader geometry: ch = 16B chunk along k (8 bf16), rr = row
    const int ch = tid & 3;
    const int rr = tid >> 2;   // 0..63
    bool aok[2]; size_t arow[2];
    #pragma unroll
    for (int it = 0; it < 2; it++) {
        int grow = m0 + rr + it * 64;
        aok[it] = grow < me;
        int gi = aok[it] ? idxs[grow] : 0;
        arow[it] = (size_t)gi * (DIMK / 8);
    }
    const size_t brow = (size_t)(n0 + rr) * (DIMK / 8);

    auto load_tiles = [&](int k0, int st) {
        __nv_bfloat16* bs = sm + st * F1_ST;
        const int kq = (k0 >> 3) + ch;
        #pragma unroll
        for (int it = 0; it < 2; it++) {
            int r = rr + it * 64;
            cp16b(bs + r * RS + ch * 8,          xh4 + arow[it] + kq, aok[it]);
            cp16b(bs + F1_AL + r * RS + ch * 8,  xl4 + arow[it] + kq, aok[it]);
        }
        cp16b(bs + F1_B1H + rr * RS + ch * 8, w1h4 + brow + kq, true);
        cp16b(bs + F1_B1L + rr * RS + ch * 8, w1l4 + brow + kq, true);
        cp16b(bs + F1_B3H + rr * RS + ch * 8, w3h4 + brow + kq, true);
        cp16b(bs + F1_B3L + rr * RS + ch * 8, w3l4 + brow + kq, true);
    };

    float acc1[2][4][4] = {}, acc3[2][4][4] = {};

    load_tiles(0, 0);
    CP_COMMIT();
    CP_WAIT0();
    __syncthreads();

    int s = 0;
    for (int k0 = 0; k0 < DIMK; k0 += 32) {
        const bool pf = (k0 + 32) < DIMK;
        if (pf) { load_tiles(k0 + 32, s ^ 1); CP_COMMIT(); }

        const __nv_bfloat16* bs = sm + s * F1_ST;
        #pragma unroll
        for (int kk = 0; kk < 2; kk++) {          // two k16 steps per 32-slab
            const int kb = kk * 16 + 2 * t;
            uint32_t ah[2][4], al[2][4];
            #pragma unroll
            for (int mi = 0; mi < 2; mi++) {
                int r0 = wm * 32 + mi * 16 + g;
                ah[mi][0] = lds32(bs + r0 * RS + kb);
                ah[mi][1] = lds32(bs + (r0 + 8) * RS + kb);
                ah[mi][2] = lds32(bs + r0 * RS + kb + 8);
                ah[mi][3] = lds32(bs + (r0 + 8) * RS + kb + 8);
                al[mi][0] = lds32(bs + F1_AL + r0 * RS + kb);
                al[mi][1] = lds32(bs + F1_AL + (r0 + 8) * RS + kb);
                al[mi][2] = lds32(bs + F1_AL + r0 * RS + kb + 8);
                al[mi][3] = lds32(bs + F1_AL + (r0 + 8) * RS + kb + 8);
            }
            #pragma unroll
            for (int ni = 0; ni < 4; ni++) {
                int nn = wn * 32 + ni * 8 + g;
                uint32_t bh[2], bl[2];
                bh[0] = lds32(bs + F1_B1H + nn * RS + kb);
                bh[1] = lds32(bs + F1_B1H + nn * RS + kb + 8);
                bl[0] = lds32(bs + F1_B1L + nn * RS + kb);
                bl[1] = lds32(bs + F1_B1L + nn * RS + kb + 8);
                #pragma unroll
                for (int mi = 0; mi < 2; mi++) mma3(acc1[mi][ni], ah[mi], al[mi], bh, bl);
                bh[0] = lds32(bs + F1_B3H + nn * RS + kb);
                bh[1] = lds32(bs + F1_B3H + nn * RS + kb + 8);
                bl[0] = lds32(bs + F1_B3L + nn * RS + kb);
                bl[1] = lds32(bs + F1_B3L + nn * RS + kb + 8);
                #pragma unroll
                for (int mi = 0; mi < 2; mi++) mma3(acc3[mi][ni], ah[mi], al[mi], bh, bl);
            }
        }

        if (pf) CP_WAIT0();
        __syncthreads();
        s ^= 1;
    }

    // epilogue: h = silu(h1)*h3, store bf16 hi/lo pairs
    const size_t Hbase = (size_t)e * NTOK * HID;
    #pragma unroll
    for (int mi = 0; mi < 2; mi++)
        #pragma unroll
        for (int ni = 0; ni < 4; ni++) {
            int rbase = wm * 32 + mi * 16 + g;
            int cbase = wn * 32 + ni * 8 + t * 2;
            #pragma unroll
            for (int h2 = 0; h2 < 2; h2++) {
                int grow = m0 + rbase + h2 * 8;
                if (grow < me) {
                    float v0 = silu_f(acc1[mi][ni][h2 * 2 + 0]) * acc3[mi][ni][h2 * 2 + 0];
                    float v1 = silu_f(acc1[mi][ni][h2 * 2 + 1]) * acc3[mi][ni][h2 * 2 + 1];
                    __nv_bfloat16 h0, h1, l0, l1;
                    bsplit(v0, h0, l0);
                    bsplit(v1, h1, l1);
                    size_t off = Hbase + (size_t)grow * HID + n0 + cbase;
                    *reinterpret_cast<__nv_bfloat162*>(&d_Hh[off]) = __nv_bfloat162(h0, h1);
                    *reinterpret_cast<__nv_bfloat162*>(&d_Hl[off]) = __nv_bfloat162(l0, l1);
                }
            }
        }
}

// ---------------- GEMM2: Y = H @ W2^T, bf16x3 --------------------------------
// smem per stage (bf16): [Ah 128*RS][Al 128*RS][Bh 64*RS][Bl 64*RS]
#define F2_AL (128 * RS)
#define F2_BH (256 * RS)
#define F2_BL (320 * RS)
#define F2_ST (384 * RS)

__global__ __launch_bounds__(256, 2) void ffn2_kernel() {
    const int e = blockIdx.z;
    const int me = d_cnt[e];
    const int m0 = blockIdx.y * 128;
    if (m0 >= me) return;
    const int n0 = blockIdx.x * 64;

    extern __shared__ __align__(16) __nv_bfloat16 sm[];

    const int tid = threadIdx.x;
    const int warp = tid >> 5, lane = tid & 31;
    const int wm = warp >> 1, wn = warp & 1;
    const int g = lane >> 2, t = lane & 3;

    const float4* Hh4 = reinterpret_cast<const float4*>(d_Hh + (size_t)e * NTOK * HID);
    const float4* Hl4 = reinterpret_cast<const float4*>(d_Hl + (size_t)e * NTOK * HID);
    const float4* w2h4 = reinterpret_cast<const float4*>(d_w2h + (size_t)e * DIMK * HID);
    const float4* w2l4 = reinterpret_cast<const float4*>(d_w2l + (size_t)e * DIMK * HID);

    const int ch = tid & 3;
    const int rr = tid >> 2;
    bool aok[2]; size_t arow[2];
    #pragma unroll
    for (int it = 0; it < 2; it++) {
        int grow = m0 + rr + it * 64;
        aok[it] = grow < me;
        arow[it] = (size_t)(aok[it] ? grow : 0) * (HID / 8);
    }
    const size_t brow = (size_t)(n0 + rr) * (HID / 8);

    auto load_tiles = [&](int k0, int st) {
        __nv_bfloat16* bs = sm + st * F2_ST;
        const int kq = (k0 >> 3) + ch;
        #pragma unroll
        for (int it = 0; it < 2; it++) {
            int r = rr + it * 64;
            cp16b(bs + r * RS + ch * 8,         Hh4 + arow[it] + kq, aok[it]);
            cp16b(bs + F2_AL + r * RS + ch * 8, Hl4 + arow[it] + kq, aok[it]);
        }
        cp16b(bs + F2_BH + rr * RS + ch * 8, w2h4 + brow + kq, true);
        cp16b(bs + F2_BL + rr * RS + ch * 8, w2l4 + brow + kq, true);
    };

    float acc[2][4][4] = {};

    load_tiles(0, 0);
    CP_COMMIT();
    CP_WAIT0();
    __syncthreads();

    int s = 0;
    for (int k0 = 0; k0 < HID; k0 += 32) {
        const bool pf = (k0 + 32) < HID;
        if (pf) { load_tiles(k0 + 32, s ^ 1); CP_COMMIT(); }

        const __nv_bfloat16* bs = sm + s * F2_ST;
        #pragma unroll
        for (int kk = 0; kk < 2; kk++) {
            const int kb = kk * 16 + 2 * t;
            uint32_t ah[2][4], al[2][4];
            #pragma unroll
            for (int mi = 0; mi < 2; mi++) {
                int r0 = wm * 32 + mi * 16 + g;
                ah[mi][0] = lds32(bs + r0 * RS + kb);
                ah[mi][1] = lds32(bs + (r0 + 8) * RS + kb);
                ah[mi][2] = lds32(bs + r0 * RS + kb + 8);
                ah[mi][3] = lds32(bs + (r0 + 8) * RS + kb + 8);
                al[mi][0] = lds32(bs + F2_AL + r0 * RS + kb);
                al[mi][1] = lds32(bs + F2_AL + (r0 + 8) * RS + kb);
                al[mi][2] = lds32(bs + F2_AL + r0 * RS + kb + 8);
                al[mi][3] = lds32(bs + F2_AL + (r0 + 8) * RS + kb + 8);
            }
            #pragma unroll
            for (int ni = 0; ni < 4; ni++) {
                int nn = wn * 32 + ni * 8 + g;
                uint32_t bh[2], bl[2];
                bh[0] = lds32(bs + F2_BH + nn * RS + kb);
                bh[1] = lds32(bs + F2_BH + nn * RS + kb + 8);
                bl[0] = lds32(bs + F2_BL + nn * RS + kb);
                bl[1] = lds32(bs + F2_BL + nn * RS + kb + 8);
                #pragma unroll
                for (int mi = 0; mi < 2; mi++) mma3(acc[mi][ni], ah[mi], al[mi], bh, bl);
            }
        }

        if (pf) CP_WAIT0();
        __syncthreads();
        s ^= 1;
    }

    float* Yrow = d_Y + (size_t)e * NTOK * DIMK;
    #pragma unroll
    for (int mi = 0; mi < 2; mi++)
        #pragma unroll
        for (int ni = 0; ni < 4; ni++) {
            int rbase = wm * 32 + mi * 16 + g;
            int cbase = wn * 32 + ni * 8 + t * 2;
            #pragma unroll
            for (int h2 = 0; h2 < 2; h2++) {
                int grow = m0 + rbase + h2 * 8;
                if (grow < me)
                    *reinterpret_cast<float2*>(&Yrow[(size_t)grow * DIMK + n0 + cbase]) =
                        make_float2(acc[mi][ni][h2 * 2 + 0], acc[mi][ni][h2 * 2 + 1]);
            }
        }
}

// out[n] = w0 * Y[e0][s0] + w1 * Y[e1][s1]
__global__ __launch_bounds__(256) void combine_kernel(float* __restrict__ out) {
    const int n = blockIdx.x;
    const int t = threadIdx.x;
    const int e0 = d_tok_e[2 * n], e1 = d_tok_e[2 * n + 1];
    const int s0 = d_tok_s[2 * n], s1 = d_tok_s[2 * n + 1];
    const float w0 = d_tok_w[2 * n], w1 = d_tok_w[2 * n + 1];

    const float4* y0 = reinterpret_cast<const float4*>(d_Y + ((size_t)e0 * NTOK + s0) * DIMK);
    const float4* y1 = reinterpret_cast<const float4*>(d_Y + ((size_t)e1 * NTOK + s1) * DIMK);
    float4 a = y0[t], b = y1[t];
    float4 r;
    r.x = w0 * a.x + w1 * b.x;
    r.y = w0 * a.y + w1 * b.y;
    r.z = w0 * a.z + w1 * b.z;
    r.w = w0 * a.w + w1 * b.w;
    reinterpret_cast<float4*>(out)[(size_t)n * (DIMK / 4) + t] = r;
}

__global__ void tail_zero_kernel(float* __restrict__ out, int start, int total) {
    int i = start + blockIdx.x * blockDim.x + threadIdx.x;
    if (i < total) out[i] = 0.f;
}

// ---------------- launch -----------------------------------------------------
extern "C" void kernel_launch(void* const* d_in, const int* in_sizes, int n_in,
                              void* d_out, int out_size) {
    const float* x    = (const float*)d_in[0];
    const float* gw   = (const float*)d_in[1];
    const float* w1   = (const float*)d_in[2];
    const float* w2   = (const float*)d_in[3];
    const float* w3   = (const float*)d_in[4];
    float* out = (float*)d_out;

    const int smem1 = 2 * F1_ST * 2;  // 81920 B (x2 CTAs/SM = 163840 <= 227KB)
    const int smem2 = 2 * F2_ST * 2;  // 61440 B
    cudaFuncSetAttribute(ffn1_kernel, cudaFuncAttributeMaxDynamicSharedMemorySize, smem1);
    cudaFuncSetAttribute(ffn2_kernel, cudaFuncAttributeMaxDynamicSharedMemorySize, smem2);

    zero_cnt_kernel<<<1, 32>>>();
    gate_kernel<<<NTOK / 8, 256>>>(x, gw);

    const int n4x = NTOK * DIMK / 4;
    const int n4w = NE * HID * DIMK / 4;
    split_kernel<<<(n4x + 255) / 256, 256>>>(x,  0, n4x);
    split_kernel<<<(n4w + 255) / 256, 256>>>(w1, 1, n4w);
    split_kernel<<<(n4w + 255) / 256, 256>>>(w3, 2, n4w);
    split_kernel<<<(n4w + 255) / 256, 256>>>(w2, 3, n4w);

    ffn1_kernel<<<dim3(HID / 64, NTOK / 128, NE), 256, smem1>>>();
    ffn2_kernel<<<dim3(DIMK / 64, NTOK / 128, NE), 256, smem2>>>();
    combine_kernel<<<NTOK, 256>>>(out);

    int main_elems = NTOK * DIMK;
    if (out_size > main_elems) {
        int tail = out_size - main_elems;
        tail_zero_kernel<<<(tail + 255) / 256, 256>>>(out, main_elems, out_size);
    }
}